// round 1
// baseline (speedup 1.0000x reference)
#include <cuda_runtime.h>

#define MARGIN 0.2f

static const int TPB  = 256;   // threads per block (pair kernel)
static const int TILE = 512;   // i-tile and j-tile extent (IPT = 2)

__device__ double g_rank_sum;
__device__ double g_m[5];  // sum_p, sum_p2, sum_t, sum_t2, sum_diff2

// ---------------------------------------------------------------------------
// Kernel 1: O(N) moments (single block) + zero the rank accumulator.
// ---------------------------------------------------------------------------
__global__ void moments_kernel(const float* __restrict__ p,
                               const float* __restrict__ t, int n) {
    __shared__ double sh[5][256];
    double sp = 0.0, sp2 = 0.0, st = 0.0, st2 = 0.0, sd2 = 0.0;
    for (int i = threadIdx.x; i < n; i += blockDim.x) {
        double pv = (double)p[i];
        double tv = (double)t[i];
        sp  += pv;
        sp2 += pv * pv;
        st  += tv;
        st2 += tv * tv;
        double d = pv - tv;
        sd2 += d * d;
    }
    sh[0][threadIdx.x] = sp;
    sh[1][threadIdx.x] = sp2;
    sh[2][threadIdx.x] = st;
    sh[3][threadIdx.x] = st2;
    sh[4][threadIdx.x] = sd2;
    __syncthreads();
    for (int off = 128; off > 0; off >>= 1) {
        if (threadIdx.x < off) {
            #pragma unroll
            for (int q = 0; q < 5; q++)
                sh[q][threadIdx.x] += sh[q][threadIdx.x + off];
        }
        __syncthreads();
    }
    if (threadIdx.x == 0) {
        #pragma unroll
        for (int q = 0; q < 5; q++) g_m[q] = sh[q][0];
        g_rank_sum = 0.0;  // reset before pair kernel (stream-ordered)
    }
}

// ---------------------------------------------------------------------------
// Kernel 2: triangular-tiled pairwise ranking loss.
// Block (c, r) with c >= r covers i in [r*TILE, r*TILE+TILE),
// j in [c*TILE, c*TILE+TILE); c == r masks to j > i.
// Each thread owns i0 = base+tid and i1 = base+tid+256 (IPT=2).
// per_pair = (|dt| > m) ? relu(m - sign(dt)*dp) : 0.1*|dp|, summed.
// ---------------------------------------------------------------------------
__global__ __launch_bounds__(TPB) void pair_kernel(const float* __restrict__ pr,
                                                   const float* __restrict__ tg,
                                                   int n) {
    const int r = blockIdx.y;
    const int c = blockIdx.x;
    if (c < r) return;  // below diagonal: no work

    __shared__ float2 sj[TILE];
    __shared__ double sred[TPB];

    const int j0 = c * TILE;
    const int jcnt = min(TILE, n - j0);

    for (int k = threadIdx.x; k < jcnt; k += TPB) {
        int j = j0 + k;
        sj[k] = make_float2(pr[j], tg[j]);
    }
    __syncthreads();

    const int i0 = r * TILE + threadIdx.x;
    const int i1 = i0 + TPB;
    const bool v0 = (i0 < n);
    const bool v1 = (i1 < n);
    const float p0 = v0 ? pr[i0] : 0.f;
    const float t0 = v0 ? tg[i0] : 0.f;
    const float p1 = v1 ? pr[i1] : 0.f;
    const float t1 = v1 ? tg[i1] : 0.f;

    float ah0 = 0.f, am0 = 0.f, ah1 = 0.f, am1 = 0.f;

    if (c > r) {
        // interior tile: every j > every i, no masking
        #pragma unroll 4
        for (int k = 0; k < jcnt; k++) {
            float2 v = sj[k];
            {
                float dp = p0 - v.x;
                float dt = t0 - v.y;
                float u = __int_as_float(__float_as_int(dp) ^
                          (__float_as_int(dt) & 0x80000000u));
                float h = fmaxf(MARGIN - u, 0.f);
                if (fabsf(dt) > MARGIN) ah0 += h; else am0 += fabsf(dp);
            }
            {
                float dp = p1 - v.x;
                float dt = t1 - v.y;
                float u = __int_as_float(__float_as_int(dp) ^
                          (__float_as_int(dt) & 0x80000000u));
                float h = fmaxf(MARGIN - u, 0.f);
                if (fabsf(dt) > MARGIN) ah1 += h; else am1 += fabsf(dp);
            }
        }
    } else {
        // diagonal tile: mask to j > i; j0 == r*TILE so j>i0 <=> k > tid
        #pragma unroll 4
        for (int k = 0; k < jcnt; k++) {
            float2 v = sj[k];
            if (k > (int)threadIdx.x) {
                float dp = p0 - v.x;
                float dt = t0 - v.y;
                float u = __int_as_float(__float_as_int(dp) ^
                          (__float_as_int(dt) & 0x80000000u));
                float h = fmaxf(MARGIN - u, 0.f);
                if (fabsf(dt) > MARGIN) ah0 += h; else am0 += fabsf(dp);
            }
            if (k > (int)threadIdx.x + TPB) {
                float dp = p1 - v.x;
                float dt = t1 - v.y;
                float u = __int_as_float(__float_as_int(dp) ^
                          (__float_as_int(dt) & 0x80000000u));
                float h = fmaxf(MARGIN - u, 0.f);
                if (fabsf(dt) > MARGIN) ah1 += h; else am1 += fabsf(dp);
            }
        }
    }

    double mine = 0.0;
    if (v0) mine += (double)ah0 + 0.1 * (double)am0;
    if (v1) mine += (double)ah1 + 0.1 * (double)am1;
    sred[threadIdx.x] = mine;
    __syncthreads();
    for (int off = 128; off > 0; off >>= 1) {
        if (threadIdx.x < off) sred[threadIdx.x] += sred[threadIdx.x + off];
        __syncthreads();
    }
    if (threadIdx.x == 0) atomicAdd(&g_rank_sum, sred[0]);
}

// ---------------------------------------------------------------------------
// Kernel 3: combine MSE + rank + diversity into the scalar output.
// ---------------------------------------------------------------------------
__global__ void finalize_kernel(float* __restrict__ out, int n) {
    double sp = g_m[0], sp2 = g_m[1], st = g_m[2], st2 = g_m[3], sd2 = g_m[4];
    double nn = (double)n;
    double mse  = sd2 / nn;
    double pvar = (sp2 - sp * sp / nn) / (nn - 1.0);
    double tvar = (st2 - st * st / nn) / (nn - 1.0);
    double divl = fmax(tvar - pvar, 0.0);
    double pc   = nn * (nn - 1.0) * 0.5;
    double rank = g_rank_sum / pc;
    out[0] = (float)(0.1 * mse + 0.9 * rank + 0.1 * divl);
}

extern "C" void kernel_launch(void* const* d_in, const int* in_sizes, int n_in,
                              void* d_out, int out_size) {
    const float* pred = (const float*)d_in[0];
    const float* targ = (const float*)d_in[1];
    int n = in_sizes[0];

    moments_kernel<<<1, 256>>>(pred, targ, n);

    int G = (n + TILE - 1) / TILE;
    dim3 grid(G, G);
    pair_kernel<<<grid, TPB>>>(pred, targ, n);

    finalize_kernel<<<1, 1>>>((float*)d_out, n);
}

// round 2
// speedup vs baseline: 2.7699x; 2.7699x over previous
#include <cuda_runtime.h>

#define MARGIN 0.2f
#define TPB  256
#define TILE 256
#define NWARP (TPB / 32)

__device__ double g_rank_sum;
__device__ double g_m[5];  // sum_p, sum_p2, sum_t, sum_t2, sum_diff2

// ---------------------------------------------------------------------------
// Zero the global accumulators (graph-replayed every iteration).
// ---------------------------------------------------------------------------
__global__ void init_kernel() {
    if (threadIdx.x == 0) g_rank_sum = 0.0;
    if (threadIdx.x < 5)  g_m[threadIdx.x] = 0.0;
}

// ---------------------------------------------------------------------------
// Triangular-tiled pairwise ranking loss + fused O(N) moments.
// Block (c, r), c >= r: i in [r*TILE, ...), j in [c*TILE, ...).
// Diagonal blocks (c == r) additionally compute this i-range's moment
// contributions (each element belongs to exactly one diagonal block).
// per_pair = (|dt| > m) ? relu(m - sign(dt)*dp) : 0.1*|dp|  (branchless FSEL)
// ---------------------------------------------------------------------------
__global__ __launch_bounds__(TPB) void pair_kernel(const float* __restrict__ pr,
                                                   const float* __restrict__ tg,
                                                   int n) {
    const int r = blockIdx.y;
    const int c = blockIdx.x;
    if (c < r) return;

    __shared__ float2 sj[TILE];
    __shared__ double swarp[NWARP];
    __shared__ double smom[5][NWARP];

    const int tid  = threadIdx.x;
    const int lane = tid & 31;
    const int wid  = tid >> 5;

    const int j0   = c * TILE;
    const int jcnt = min(TILE, n - j0);
    if (tid < jcnt) {
        int j = j0 + tid;
        sj[tid] = make_float2(pr[j], tg[j]);
    }
    __syncthreads();

    const int  i  = r * TILE + tid;
    const bool vi = (i < n);
    const float p0 = vi ? pr[i] : 0.f;
    const float t0 = vi ? tg[i] : 0.f;

    float acc0 = 0.f, acc1 = 0.f;
    if (vi) {
        int k = (c == r) ? tid + 1 : 0;   // diagonal: strictly j > i, no masking
        #pragma unroll 4
        for (; k + 1 < jcnt; k += 2) {
            {
                float2 v = sj[k];
                float dp = p0 - v.x;
                float dt = t0 - v.y;
                float u  = __uint_as_float(__float_as_uint(dp) ^
                           (__float_as_uint(dt) & 0x80000000u));
                float h  = fmaxf(MARGIN - u, 0.0f);
                acc0 += (fabsf(dt) > MARGIN) ? h : 0.1f * fabsf(dp);
            }
            {
                float2 v = sj[k + 1];
                float dp = p0 - v.x;
                float dt = t0 - v.y;
                float u  = __uint_as_float(__float_as_uint(dp) ^
                           (__float_as_uint(dt) & 0x80000000u));
                float h  = fmaxf(MARGIN - u, 0.0f);
                acc1 += (fabsf(dt) > MARGIN) ? h : 0.1f * fabsf(dp);
            }
        }
        if (k < jcnt) {
            float2 v = sj[k];
            float dp = p0 - v.x;
            float dt = t0 - v.y;
            float u  = __uint_as_float(__float_as_uint(dp) ^
                       (__float_as_uint(dt) & 0x80000000u));
            float h  = fmaxf(MARGIN - u, 0.0f);
            acc0 += (fabsf(dt) > MARGIN) ? h : 0.1f * fabsf(dp);
        }
    }

    // ---- rank reduction: warp shuffle -> shared -> one atomic per block ----
    double mine = (double)acc0 + (double)acc1;
    #pragma unroll
    for (int o = 16; o > 0; o >>= 1)
        mine += __shfl_down_sync(0xFFFFFFFFu, mine, o);
    if (lane == 0) swarp[wid] = mine;

    // ---- moments (diagonal blocks only; uniform branch per block) ----
    if (c == r) {
        double pv = vi ? (double)p0 : 0.0;
        double tv = vi ? (double)t0 : 0.0;
        double d  = pv - tv;
        double m[5] = { pv, pv * pv, tv, tv * tv, d * d };
        #pragma unroll
        for (int q = 0; q < 5; q++) {
            #pragma unroll
            for (int o = 16; o > 0; o >>= 1)
                m[q] += __shfl_down_sync(0xFFFFFFFFu, m[q], o);
            if (lane == 0) smom[q][wid] = m[q];
        }
    }

    __syncthreads();

    if (wid == 0) {
        double v = (lane < NWARP) ? swarp[lane] : 0.0;
        #pragma unroll
        for (int o = 4; o > 0; o >>= 1)
            v += __shfl_down_sync(0xFFFFFFFFu, v, o);
        if (lane == 0) atomicAdd(&g_rank_sum, v);
    }
    if (c == r && wid == 1) {
        #pragma unroll
        for (int q = 0; q < 5; q++) {
            double v = (lane < NWARP) ? smom[q][lane] : 0.0;
            #pragma unroll
            for (int o = 4; o > 0; o >>= 1)
                v += __shfl_down_sync(0xFFFFFFFFu, v, o);
            if (lane == 0) atomicAdd(&g_m[q], v);
        }
    }
}

// ---------------------------------------------------------------------------
// Combine MSE + rank + diversity into the scalar output.
// ---------------------------------------------------------------------------
__global__ void finalize_kernel(float* __restrict__ out, int n) {
    double sp = g_m[0], sp2 = g_m[1], st = g_m[2], st2 = g_m[3], sd2 = g_m[4];
    double nn = (double)n;
    double mse  = sd2 / nn;
    double pvar = (sp2 - sp * sp / nn) / (nn - 1.0);
    double tvar = (st2 - st * st / nn) / (nn - 1.0);
    double divl = fmax(tvar - pvar, 0.0);
    double pc   = nn * (nn - 1.0) * 0.5;
    double rank = g_rank_sum / pc;
    out[0] = (float)(0.1 * mse + 0.9 * rank + 0.1 * divl);
}

extern "C" void kernel_launch(void* const* d_in, const int* in_sizes, int n_in,
                              void* d_out, int out_size) {
    const float* pred = (const float*)d_in[0];
    const float* targ = (const float*)d_in[1];
    int n = in_sizes[0];

    init_kernel<<<1, 32>>>();

    int G = (n + TILE - 1) / TILE;
    dim3 grid(G, G);
    pair_kernel<<<grid, TPB>>>(pred, targ, n);

    finalize_kernel<<<1, 1>>>((float*)d_out, n);
}

// round 3
// speedup vs baseline: 2.7946x; 1.0089x over previous
#include <cuda_runtime.h>

#define MARGIN 0.2f
#define TPB  256
#define TILE 256
#define NWARP (TPB / 32)

__device__ double g_rank_sum;
__device__ double g_m[5];        // sum_p, sum_p2, sum_t, sum_t2, sum_diff2
__device__ unsigned int g_done;  // zero-initialized; reset by last block

// ---------------------------------------------------------------------------
// Single fused kernel.
// 1D triangular grid: block b -> (r, c) with c >= r.
//   i in [r*TILE, r*TILE+TILE), j in [c*TILE, c*TILE+TILE)
// Diagonal blocks (c == r) start j at i+1 and also compute the O(N) moments
// for their i-slice. The last block to finish finalizes the scalar output
// and resets all global accumulators (graph-replay safe).
// per_pair = (|dt| > m) ? relu(m - sign(dt)*dp) : 0.1*|dp|
// ---------------------------------------------------------------------------
__global__ __launch_bounds__(TPB) void fused_kernel(const float* __restrict__ pr,
                                                    const float* __restrict__ tg,
                                                    int n, int G, int T,
                                                    float* __restrict__ out) {
    // --- recover (r, c) from linear triangular index ---
    const int b = blockIdx.x;
    double disc = (double)(2 * G + 1) * (double)(2 * G + 1) - 8.0 * (double)b;
    int r = (int)(((double)(2 * G + 1) - sqrt(disc)) * 0.5);
    // correction for fp rounding: S(r) = r*G - r*(r-1)/2 must satisfy S(r)<=b<S(r+1)
    while (r > 0 && (r * G - (r * (r - 1)) / 2) > b) --r;
    while (((r + 1) * G - ((r + 1) * r) / 2) <= b) ++r;
    const int c = r + (b - (r * G - (r * (r - 1)) / 2));
    const bool diag = (c == r);

    __shared__ float2 sj[TILE];
    __shared__ double swarp[NWARP];
    __shared__ double smom[5][NWARP];
    __shared__ bool   s_last;

    const int tid  = threadIdx.x;
    const int lane = tid & 31;
    const int wid  = tid >> 5;

    const int j0   = c * TILE;
    const int jcnt = min(TILE, n - j0);
    if (tid < jcnt) {
        int j = j0 + tid;
        sj[tid] = make_float2(pr[j], tg[j]);
    }
    __syncthreads();

    const int  i  = r * TILE + tid;
    const bool vi = (i < n);
    const float p0 = vi ? pr[i] : 0.f;
    const float t0 = vi ? tg[i] : 0.f;

    float acch = 0.f, accm = 0.f;   // hinge sum, |dp| sum (0.1 applied later)
    if (vi) {
        int k = diag ? tid + 1 : 0;
        #pragma unroll 8
        for (; k < jcnt; k++) {
            float2 v = sj[k];
            float dp = p0 - v.x;
            float dt = t0 - v.y;
            float u  = __uint_as_float(__float_as_uint(dp) ^
                       (__float_as_uint(dt) & 0x80000000u));
            float h  = fmaxf(MARGIN - u, 0.0f);
            if (fabsf(dt) > MARGIN) acch += h;
            else                    accm += fabsf(dp);
        }
    }

    // ---- rank reduction: warp shuffle -> shared -> one atomic per block ----
    double mine = (double)acch + 0.1 * (double)accm;
    #pragma unroll
    for (int o = 16; o > 0; o >>= 1)
        mine += __shfl_down_sync(0xFFFFFFFFu, mine, o);
    if (lane == 0) swarp[wid] = mine;

    // ---- moments (diagonal blocks only) ----
    if (diag) {
        double pv = vi ? (double)p0 : 0.0;
        double tv = vi ? (double)t0 : 0.0;
        double d  = pv - tv;
        double m[5] = { pv, pv * pv, tv, tv * tv, d * d };
        #pragma unroll
        for (int q = 0; q < 5; q++) {
            #pragma unroll
            for (int o = 16; o > 0; o >>= 1)
                m[q] += __shfl_down_sync(0xFFFFFFFFu, m[q], o);
            if (lane == 0) smom[q][wid] = m[q];
        }
    }

    __syncthreads();

    if (wid == 0) {
        double v = (lane < NWARP) ? swarp[lane] : 0.0;
        #pragma unroll
        for (int o = 4; o > 0; o >>= 1)
            v += __shfl_down_sync(0xFFFFFFFFu, v, o);
        if (lane == 0) atomicAdd(&g_rank_sum, v);
    }
    if (diag && wid == 1) {
        #pragma unroll
        for (int q = 0; q < 5; q++) {
            double v = (lane < NWARP) ? smom[q][lane] : 0.0;
            #pragma unroll
            for (int o = 4; o > 0; o >>= 1)
                v += __shfl_down_sync(0xFFFFFFFFu, v, o);
            if (lane == 0) atomicAdd(&g_m[q], v);
        }
    }

    // ---- last-block finalize + reset (threadfence-reduction pattern) ----
    if (tid == 0) {
        __threadfence();
        unsigned int prev = atomicAdd(&g_done, 1u);
        s_last = (prev == (unsigned int)(T - 1));
    }
    __syncthreads();

    if (s_last && tid == 0) {
        double sp = g_m[0], sp2 = g_m[1], st = g_m[2], st2 = g_m[3], sd2 = g_m[4];
        double nn = (double)n;
        double mse  = sd2 / nn;
        double pvar = (sp2 - sp * sp / nn) / (nn - 1.0);
        double tvar = (st2 - st * st / nn) / (nn - 1.0);
        double divl = fmax(tvar - pvar, 0.0);
        double pc   = nn * (nn - 1.0) * 0.5;
        double rank = g_rank_sum / pc;
        out[0] = (float)(0.1 * mse + 0.9 * rank + 0.1 * divl);
        // reset for next graph replay
        g_rank_sum = 0.0;
        #pragma unroll
        for (int q = 0; q < 5; q++) g_m[q] = 0.0;
        g_done = 0u;
    }
}

extern "C" void kernel_launch(void* const* d_in, const int* in_sizes, int n_in,
                              void* d_out, int out_size) {
    const float* pred = (const float*)d_in[0];
    const float* targ = (const float*)d_in[1];
    int n = in_sizes[0];

    int G = (n + TILE - 1) / TILE;
    int T = G * (G + 1) / 2;
    fused_kernel<<<T, TPB>>>(pred, targ, n, G, T, (float*)d_out);
}